// round 11
// baseline (speedup 1.0000x reference)
#include <cuda_runtime.h>
#include <math.h>

#define Nn     16384
#define D_INc  256
#define HIDD   256
#define D_OUTc 256
#define Ff     8
#define Ll     4
#define IN_CH  272          // 2*8 + 256
#define GAMMAf 0.5f

// ---------------- device scratch (no allocations allowed) ----------------
__device__ __align__(16) float g_cs[2][Ll][Ff];
__device__ __align__(16) float g_Hm[Nn][16];      // cols 0-7: tri, 8-15: cl4

__device__ __forceinline__ float softplusf(float x) {
    return (x > 20.f) ? x : log1pf(expf(x));
}

__device__ __forceinline__ void red4(float* p, float a, float b, float c, float d) {
    asm volatile("red.global.add.v4.f32 [%0], {%1, %2, %3, %4};"
                 :: "l"(p), "f"(a), "f"(b), "f"(c), "f"(d) : "memory");
}

// packed dual-fp32 FMA (Blackwell f32x2) -------------------------------
#define FFMA2(acc, a, b) \
    asm("fma.rn.f32x2 %0, %1, %2, %0;" : "+l"(acc) : "l"(a), "l"(b))
#define DUP2(p, x) \
    asm("mov.b64 %0, {%1, %1};" : "=l"(p) : "r"(x))
#define UNPK2(lo, hi, p) \
    asm("mov.b64 {%0, %1}, %2;" : "=r"(lo), "=r"(hi) : "l"(p))

// register-free async gmem->smem 16B copy (LDGSTS)
#define CPA16(dst, src) do {                                              \
    unsigned _s = (unsigned)__cvta_generic_to_shared(dst);                \
    asm volatile("cp.async.cg.shared.global [%0], [%1], 16;"              \
                 :: "r"(_s), "l"(src));                                   \
} while (0)
#define CP_COMMIT() asm volatile("cp.async.commit_group;" ::: "memory")
#define CP_WAIT0()  asm volatile("cp.async.wait_group 0;" ::: "memory")

// ---------------- kernel 1: filter traces + coefficients ----------------
__global__ void setup_kernel(const float* __restrict__ Wt,
                             const float* __restrict__ Wc,
                             const float* __restrict__ lg) {
    int t = threadIdx.x;
    if (t >= 16) return;
    int which = t >> 3;
    int f = t & 7;
    int S = which ? 4 : 3;
    const float* W = which ? (Wc + f * 16) : (Wt + f * 9);

    float Wm[4][4], Sf[4][4];
    for (int i = 0; i < S; i++)
        for (int j = 0; j < S; j++)
            Wm[i][j] = softplusf(W[i * S + j]);
    for (int i = 0; i < S; i++)
        for (int j = 0; j < S; j++)
            Sf[i][j] = 0.5f * (Wm[i][j] + Wm[j][i]);
    for (int i = 0; i < S; i++) Sf[i][i] = 0.f;
    for (int i = 0; i < S; i++) {
        float rs = 0.f;
        for (int j = 0; j < S; j++) rs += Sf[i][j];
        float inv = 1.f / fmaxf(rs, 1e-12f);
        for (int j = 0; j < S; j++) Sf[i][j] *= inv;
    }
    float P[4][4], Q[4][4], tr[Ll];
    for (int i = 0; i < S; i++)
        for (int j = 0; j < S; j++) P[i][j] = Sf[i][j];
    for (int l = 0; l < Ll; l++) {
        if (l) {
            for (int i = 0; i < S; i++)
                for (int j = 0; j < S; j++) {
                    float a = 0.f;
                    for (int k = 0; k < S; k++) a += P[i][k] * Sf[k][j];
                    Q[i][j] = a;
                }
            for (int i = 0; i < S; i++)
                for (int j = 0; j < S; j++) P[i][j] = Q[i][j];
        }
        float s = 0.f;
        for (int i = 0; i < S; i++) s += P[i][i];
        tr[l] = s;
    }
    for (int l = 0; l < Ll; l++) {
        float coeff = powf(GAMMAf, (float)(l + 1)) * softplusf(lg[l]);
        g_cs[which][l][f] = tr[l] * coeff;
    }
}

// ---------------- kernel 2: zero the motif accumulator ----------------
__global__ void zero_kernel() {
    int i = blockIdx.x * blockDim.x + threadIdx.x;
    if (i < Nn * 16) ((float*)g_Hm)[i] = 0.f;
}

// ---------------- motif math (per motif, after gather) ----------------
template <int S>
__device__ __forceinline__ void motif_math(float (&T)[S][S],
                                           const int (&nd)[S], int which) {
#pragma unroll
    for (int i = 0; i < S; i++) {
        float rs = 0.f;
#pragma unroll
        for (int j = 0; j < S; j++) rs += T[i][j];
        float inv = 1.f / fmaxf(rs, 1e-12f);
#pragma unroll
        for (int j = 0; j < S; j++) T[i][j] *= inv;
    }

    float P[S][S], Q[S][S], tr[Ll];
#pragma unroll
    for (int i = 0; i < S; i++)
#pragma unroll
        for (int j = 0; j < S; j++) P[i][j] = T[i][j];
    {
        float s = 0.f;
#pragma unroll
        for (int i = 0; i < S; i++) s += P[i][i];
        tr[0] = s;
    }
#pragma unroll
    for (int l = 1; l < Ll; l++) {
#pragma unroll
        for (int i = 0; i < S; i++)
#pragma unroll
            for (int j = 0; j < S; j++) {
                float a = 0.f;
#pragma unroll
                for (int k = 0; k < S; k++) a += P[i][k] * T[k][j];
                Q[i][j] = a;
            }
        float s = 0.f;
#pragma unroll
        for (int i = 0; i < S; i++) {
#pragma unroll
            for (int j = 0; j < S; j++) P[i][j] = Q[i][j];
            s += P[i][i];
        }
        tr[l] = s;
    }

    float sims[Ff];
#pragma unroll
    for (int f = 0; f < Ff; f++) {
        float s = 0.f;
#pragma unroll
        for (int l = 0; l < Ll; l++) s += tr[l] * g_cs[which][l][f];
        sims[f] = s;
    }
    float mx = sims[0];
#pragma unroll
    for (int f = 1; f < Ff; f++) mx = fmaxf(mx, sims[f]);
    float e[Ff], es = 0.f;
#pragma unroll
    for (int f = 0; f < Ff; f++) { e[f] = expf(sims[f] - mx); es += e[f]; }
    float invs = 1.f / es;
    const float invS = 1.f / (float)S;
    float cb[Ff];
#pragma unroll
    for (int f = 0; f < Ff; f++) cb[f] = e[f] * invs * sims[f] * invS;

    int off = which * 8;
#pragma unroll
    for (int i = 0; i < S; i++) {
        float* p = &g_Hm[nd[i]][off];
        red4(p,     cb[0], cb[1], cb[2], cb[3]);
        red4(p + 4, cb[4], cb[5], cb[6], cb[7]);
    }
}

// two motifs per thread: gathers hoisted together for 2x memory-level parallelism
template <int S>
__device__ __forceinline__ void motif_body2(const float* __restrict__ A,
                                            const int* __restrict__ nodes,
                                            int M, int which, int bid) {
    int half = (M + 1) >> 1;
    int m0 = bid * 256 + threadIdx.x;
    if (m0 >= half) return;
    int m1 = m0 + half;
    bool has1 = (m1 < M);

    int nd0[S], nd1[S];
#pragma unroll
    for (int i = 0; i < S; i++) nd0[i] = nodes[m0 * S + i];
#pragma unroll
    for (int i = 0; i < S; i++) nd1[i] = has1 ? nodes[m1 * S + i] : 0;

    float T0[S][S], T1[S][S];
#pragma unroll
    for (int i = 0; i < S; i++) {
        const float* rp = A + (size_t)nd0[i] * Nn;
#pragma unroll
        for (int j = 0; j < S; j++) T0[i][j] = __ldg(rp + nd0[j]);
    }
#pragma unroll
    for (int i = 0; i < S; i++) {
        const float* rp = A + (size_t)nd1[i] * Nn;
#pragma unroll
        for (int j = 0; j < S; j++) T1[i][j] = has1 ? __ldg(rp + nd1[j]) : 1.f;
    }

    motif_math<S>(T0, nd0, which);
    if (has1) motif_math<S>(T1, nd1, which);
}

__global__ void motif_all_kernel(const float* __restrict__ A,
                                 const int* __restrict__ nt, int Mt, int nb3,
                                 const int* __restrict__ nc, int Mc) {
    if ((int)blockIdx.x < nb3)
        motif_body2<3>(A, nt, Mt, 0, blockIdx.x);
    else
        motif_body2<4>(A, nc, Mc, 1, blockIdx.x - nb3);
}

// ---------------- fused concat + LN + MLP ----------------
// 32 rows/block, 128 threads. Warp w owns output cols [64w,64w+64):
// warp-private W tiles (own cp.async groups) -> NO block barrier in mainloops.
// Thread tile: 16 row-pairs x 2 cols; x pairs loaded packed (no DUP2 on x).
#define ROWS  32
#define TPB   128
#define BK    8
#define XS    36                  // padded row stride in sXT

__global__ __launch_bounds__(TPB, 4) void mlp_kernel(
    const float* __restrict__ H_in, const float* __restrict__ ln_g,
    const float* __restrict__ ln_b,
    const float* __restrict__ W1, const float* __restrict__ b1,
    const float* __restrict__ W2, const float* __restrict__ b2,
    float* __restrict__ out) {
    __shared__ float sXT[IN_CH * XS];        // [k][row] transposed acts
    __shared__ float sWp[4][2][BK * 64];     // per-warp double-buffered W slice

    const int tid  = threadIdx.x;
    const int warp = tid >> 5;
    const int lane = tid & 31;
    const int rbase = blockIdx.x * ROWS;

    const int cloc  = lane * 2;              // local col within warp's 64
    const int cglob = warp * 64 + cloc;      // global output col

    // per-warp async fetch of its 64-col slice of one BK-row tile
#define CPW(Wp, kbase, BUF)                                                  \
    {                                                                        \
        _Pragma("unroll")                                                    \
        for (int q = 0; q < 4; q++) {                                        \
            int p = q * 32 + lane;                                           \
            int kk = p >> 4, cc = (p & 15) << 2;                             \
            CPA16(&sWp[warp][BUF][kk * 64 + cc],                             \
                  &Wp[(size_t)((kbase) + kk) * HIDD + warp * 64 + cc]);      \
        }                                                                    \
        CP_COMMIT();                                                         \
    }
    // compute one BK tile from the warp-private buffer
#define CT(K0, BUF)                                                          \
    {                                                                        \
        _Pragma("unroll")                                                    \
        for (int kk = 0; kk < BK; kk++) {                                    \
            const float* xb = &sXT[(K0 + kk) * XS];                          \
            unsigned long long wd0, wd1;                                     \
            float2 wv = *(const float2*)&sWp[warp][BUF][kk * 64 + cloc];     \
            DUP2(wd0, __float_as_uint(wv.x));                                \
            DUP2(wd1, __float_as_uint(wv.y));                                \
            _Pragma("unroll")                                                \
            for (int q = 0; q < 8; q++) {                                    \
                ulonglong2 xr = *(const ulonglong2*)(xb + q * 4);            \
                FFMA2(acc[q * 2][0],     xr.x, wd0);                         \
                FFMA2(acc[q * 2][1],     xr.x, wd1);                         \
                FFMA2(acc[q * 2 + 1][0], xr.y, wd0);                         \
                FFMA2(acc[q * 2 + 1][1], xr.y, wd1);                         \
            }                                                                \
        }                                                                    \
    }

    // kick off W1 tile 0 fetch (warp-private) — hides under LN
    CPW(W1, 0, 0);

    // ---- LN: warp handles 8 rows; single gmem read ----
    {
        const int r0 = warp * 8;
#pragma unroll
        for (int i = 0; i < 8; i++) {
            int r = r0 + i;
            int grow = rbase + r;
            const float* hrow = H_in + (size_t)grow * D_INc;
            float vloc[9];
            float s = 0.f, s2 = 0.f;
#pragma unroll
            for (int q = 0; q < 9; q++) {
                int c = lane + q * 32;
                if (c < IN_CH) {
                    float v = (c < 16) ? g_Hm[grow][c] : __ldg(hrow + (c - 16));
                    vloc[q] = v;
                    s += v; s2 += v * v;
                }
            }
#pragma unroll
            for (int o = 16; o; o >>= 1) {
                s  += __shfl_xor_sync(0xffffffffu, s, o);
                s2 += __shfl_xor_sync(0xffffffffu, s2, o);
            }
            float mu = s * (1.f / IN_CH);
            float var = s2 * (1.f / IN_CH) - mu * mu;
            float rstd = rsqrtf(var + 1e-5f);
#pragma unroll
            for (int q = 0; q < 9; q++) {
                int c = lane + q * 32;
                if (c < IN_CH)
                    sXT[c * XS + r] = (vloc[q] - mu) * rstd * ln_g[c] + ln_b[c];
            }
        }
    }
    CP_WAIT0();
    __syncthreads();

    unsigned long long acc[16][2];
#pragma unroll
    for (int i = 0; i < 16; i++) { acc[i][0] = 0ULL; acc[i][1] = 0ULL; }

    // ---- GEMM1: x(32x272) @ W1(272x256) — barrier-free mainloop ----
    {
        const int NT = IN_CH / BK;       // 34
        for (int t = 0; t < NT; t++) {
            if (t + 1 < NT) CPW(W1, (t + 1) * BK, (t + 1) & 1);
            CT(t * BK, t & 1);
            if (t + 1 < NT) CP_WAIT0();
            __syncwarp();
        }
    }

    // all warps must finish READING sXT before h overwrites it
    __syncthreads();

    // prefetch W2 tile 0 — hides under GELU math
    CPW(W2, 0, 0);

    // ---- bias + exact GELU -> transposed hidden into sXT ----
    {
        const float2 bb = *(const float2*)&b1[cglob];
#pragma unroll
        for (int rp = 0; rp < 16; rp++) {
            unsigned lo, hi;
            UNPK2(lo, hi, acc[rp][0]);
            float a0 = __uint_as_float(lo) + bb.x;   // row rp*2,   col cglob
            float a1 = __uint_as_float(hi) + bb.x;   // row rp*2+1, col cglob
            UNPK2(lo, hi, acc[rp][1]);
            float c0 = __uint_as_float(lo) + bb.y;   // col cglob+1
            float c1 = __uint_as_float(hi) + bb.y;
            a0 = 0.5f * a0 * (1.f + erff(a0 * 0.7071067811865475f));
            a1 = 0.5f * a1 * (1.f + erff(a1 * 0.7071067811865475f));
            c0 = 0.5f * c0 * (1.f + erff(c0 * 0.7071067811865475f));
            c1 = 0.5f * c1 * (1.f + erff(c1 * 0.7071067811865475f));
            *(float2*)&sXT[cglob * XS + rp * 2]       = make_float2(a0, a1);
            *(float2*)&sXT[(cglob + 1) * XS + rp * 2] = make_float2(c0, c1);
            acc[rp][0] = 0ULL; acc[rp][1] = 0ULL;
        }
    }
    __syncthreads();
    CP_WAIT0();

    // ---- GEMM2: h(32x256) @ W2(256x256) — barrier-free mainloop ----
    {
        const int NT = HIDD / BK;        // 32
        for (int t = 0; t < NT; t++) {
            if (t + 1 < NT) CPW(W2, (t + 1) * BK, (t + 1) & 1);
            CT(t * BK, t & 1);
            if (t + 1 < NT) CP_WAIT0();
            __syncwarp();
        }
    }

    // ---- bias + store (float2 per row, warp covers 256B contiguous) ----
    {
        const float2 bb = *(const float2*)&b2[cglob];
#pragma unroll
        for (int rp = 0; rp < 16; rp++) {
            unsigned lo0, hi0, lo1, hi1;
            UNPK2(lo0, hi0, acc[rp][0]);
            UNPK2(lo1, hi1, acc[rp][1]);
            size_t row0 = (size_t)(rbase + rp * 2) * D_OUTc;
            *(float2*)&out[row0 + cglob] =
                make_float2(__uint_as_float(lo0) + bb.x, __uint_as_float(lo1) + bb.y);
            *(float2*)&out[row0 + D_OUTc + cglob] =
                make_float2(__uint_as_float(hi0) + bb.x, __uint_as_float(hi1) + bb.y);
        }
    }
}

// ---------------- launch ----------------
extern "C" void kernel_launch(void* const* d_in, const int* in_sizes, int n_in,
                              void* d_out, int out_size) {
    const float* A       = (const float*)d_in[0];
    const float* H_in    = (const float*)d_in[1];
    const float* Wt      = (const float*)d_in[2];
    const float* Wc      = (const float*)d_in[3];
    const float* lg      = (const float*)d_in[4];
    const float* ln_g    = (const float*)d_in[5];
    const float* ln_b    = (const float*)d_in[6];
    const float* W1      = (const float*)d_in[7];
    const float* b1      = (const float*)d_in[8];
    const float* W2      = (const float*)d_in[9];
    const float* b2      = (const float*)d_in[10];
    const int* nodes_tri = (const int*)d_in[11];
    const int* nodes_cl4 = (const int*)d_in[12];
    float* out = (float*)d_out;

    int M_tri = in_sizes[11] / 3;
    int M_cl4 = in_sizes[12] / 4;
    int h3 = (M_tri + 1) >> 1, h4 = (M_cl4 + 1) >> 1;
    int nb3 = (h3 + 255) / 256;
    int nb4 = (h4 + 255) / 256;

    setup_kernel<<<1, 32>>>(Wt, Wc, lg);
    zero_kernel<<<(Nn * 16 + 255) / 256, 256>>>();
    motif_all_kernel<<<nb3 + nb4, 256>>>(A, nodes_tri, M_tri, nb3, nodes_cl4, M_cl4);
    mlp_kernel<<<Nn / ROWS, TPB>>>(H_in, ln_g, ln_b, W1, b1, W2, b2, out);
}